// round 5
// baseline (speedup 1.0000x reference)
#include <cuda_runtime.h>
#include <math.h>

// ConvCaps EM routing (b=8, B=C=32, K=3, s=2, Win=13, Wout=6, 3 EM iters).
// Fused persistent kernel, block = (xy, n-pair): each W register load serves
// votes for 2 batch elements -> W L1 wavefronts per SM halved vs round 4.
// p_hat block-local in smem; grid barrier only for the D normalizer.
// Vote math in packed fma.rn.f32x2 (d-pairs over p; pose duplicated in smem).

#define RP0 (1.0f / 1152.0f)
#define LOG2PI 1.8378770664093453f
typedef unsigned long long ull;

__device__ float g_Wt[147456];   // [o][ij][q][c][p]  (ulonglong2 per (q,c))
__device__ float g_D0[43264];    // [n][o][13][13]
__device__ float g_D1[43264];
__device__ unsigned g_bar[2];

// -------- prep: W relayout, zero D + barrier counters --------
__global__ void prep_kernel(const float* __restrict__ W) {
    int idx = blockIdx.x * 256 + threadIdx.x;
    if (idx < 147456) {
        int p = idx & 3, c = (idx >> 2) & 31, q = (idx >> 7) & 3;
        int oij = idx >> 9;
        int o = oij / 9, ij = oij - o * 9;
        // src: W[i,j,o,c,p,q]
        g_Wt[idx] = W[(((ij * 32 + o) * 32 + c) * 4 + p) * 4 + q];
    }
    if (idx < 43264) { g_D0[idx] = 0.0f; g_D1[idx] = 0.0f; }
    if (idx < 2) g_bar[idx] = 0u;
}

// -------- packed f32x2 helpers --------
__device__ __forceinline__ ull f2fma(ull a, ull b, ull c) {
    ull d; asm("fma.rn.f32x2 %0, %1, %2, %3;" : "=l"(d) : "l"(a), "l"(b), "l"(c)); return d;
}
__device__ __forceinline__ ull f2mul(ull a, ull b) {
    ull d; asm("mul.rn.f32x2 %0, %1, %2;" : "=l"(d) : "l"(a), "l"(b)); return d;
}
__device__ __forceinline__ ull f2add(ull a, ull b) {
    ull d; asm("add.rn.f32x2 %0, %1, %2;" : "=l"(d) : "l"(a), "l"(b)); return d;
}
__device__ __forceinline__ ull f2pack(float lo, float hi) {
    ull d; asm("mov.b64 %0, {%1, %2};" : "=l"(d) : "f"(lo), "f"(hi)); return d;
}
__device__ __forceinline__ void f2unpack(float& lo, float& hi, ull v) {
    asm("mov.b64 {%0, %1}, %2;" : "=f"(lo), "=f"(hi) : "l"(v));
}

// smem float offsets
#define SM_POSE 0        // [nn][oij][qr*2 dup] : 2*288*32 = 18432
#define SM_A    18432    // [nn*288+oij] : 576
#define SM_AD   19008    // 576
#define SM_PH   19584    // [nn][oij][33] : 19008 (red 16*1056=16896 aliased)
#define SM_MOM  38592    // [nn][c][33] : 2112
#define SM_MU   40704    // [nn][c][17] : 1088
#define SM_SFAC 41792    // [nn*32+c] : 64
#define SMEM_FLOATS 41856

__global__ void __launch_bounds__(512, 1) fused_kernel(
    const float* __restrict__ x,
    const float* __restrict__ bv_p,
    const float* __restrict__ ba_p,
    const float* __restrict__ lam_p,
    float* __restrict__ out)
{
    extern __shared__ float sm[];
    float* pose2  = sm + SM_POSE;
    float* a_s    = sm + SM_A;
    float* aD_s   = sm + SM_AD;
    float* ph_s   = sm + SM_PH;
    float* red    = ph_s;          // aliased
    float* mom    = sm + SM_MOM;
    float* mu_s   = sm + SM_MU;
    float* sfac_s = sm + SM_SFAC;

    const int xy = blockIdx.x;     // 0..35
    const int np = blockIdx.y;     // 0..3  -> n = 2*np + nn
    const int X = xy / 6, Y = xy % 6;
    const int tid = threadIdx.x;
    const int w = tid >> 5;        // 0..15
    const int c = tid & 31;
    const int base = (2 * X) * 13 + 2 * Y;

    // ---- load patches for both n ----
    for (int e = tid; e < 1024; e += 512) {
        int nn = e >> 9, rem = e & 511;
        int qr = rem & 15, o = rem >> 4;
        const float* src = x + (2 * np + nn) * 91936 + (qr * 32 + o) * 169 + base;
        float* dst = pose2 + nn * 9216 + (o * 9) * 32 + qr * 2;
        #pragma unroll
        for (int i = 0; i < 3; i++)
            #pragma unroll
            for (int j = 0; j < 3; j++) {
                float v = src[i * 13 + j];
                int off = (i * 3 + j) * 32;
                dst[off] = v; dst[off + 1] = v;
            }
    }
    for (int e = tid; e < 576; e += 512) {
        int nn = (e >= 288) ? 1 : 0;
        int oij = e - nn * 288;
        int o = oij / 9, ij = oij - o * 9;
        float av = x[(2 * np + nn) * 91936 + (512 + o) * 169 + base + (ij / 3) * 13 + (ij % 3)];
        a_s[e] = av;
        aD_s[e] = av * RP0;        // iter0: rh = 1 * aD
    }
    for (int e = tid; e < 19008; e += 512) ph_s[e] = 1.0f;
    __syncthreads();

    const float bv = bv_p[0], ba = ba_p[0], lam = lam_p[0];

    for (int it = 0; it < 3; it++) {
        // ================= M phase =================
        ull m1a[2][4], m1b[2][4], m2a[2][4], m2b[2][4];
        float sumr[2] = {0.0f, 0.0f};
        #pragma unroll
        for (int nn = 0; nn < 2; nn++)
            #pragma unroll
            for (int r = 0; r < 4; r++) { m1a[nn][r]=0ull; m1b[nn][r]=0ull; m2a[nn][r]=0ull; m2b[nn][r]=0ull; }

        #pragma unroll 1
        for (int oo = 0; oo < 2; oo++) {
            int o = w * 2 + oo;
            #pragma unroll 3
            for (int ij = 0; ij < 9; ij++) {
                int oij = o * 9 + ij;
                const ulonglong2* wp = (const ulonglong2*)g_Wt + (oij * 4) * 32 + c;
                ulonglong2 wv0 = wp[0], wv1 = wp[32], wv2 = wp[64], wv3 = wp[96];
                #pragma unroll
                for (int nn = 0; nn < 2; nn++) {
                    float rh = ph_s[nn * 9504 + oij * 33 + c] * aD_s[nn * 288 + oij];
                    sumr[nn] += rh;
                    ull rh2 = f2pack(rh, rh);
                    const ull* pb = (const ull*)(pose2 + nn * 9216 + oij * 32);
                    ull v0[4], v1[4];
                    #pragma unroll
                    for (int r = 0; r < 4; r++) {
                        ull P = pb[r];
                        v0[r] = f2mul(wv0.x, P); v1[r] = f2mul(wv0.y, P);
                    }
                    #pragma unroll
                    for (int r = 0; r < 4; r++) {
                        ull P = pb[4 + r];
                        v0[r] = f2fma(wv1.x, P, v0[r]); v1[r] = f2fma(wv1.y, P, v1[r]);
                    }
                    #pragma unroll
                    for (int r = 0; r < 4; r++) {
                        ull P = pb[8 + r];
                        v0[r] = f2fma(wv2.x, P, v0[r]); v1[r] = f2fma(wv2.y, P, v1[r]);
                    }
                    #pragma unroll
                    for (int r = 0; r < 4; r++) {
                        ull P = pb[12 + r];
                        v0[r] = f2fma(wv3.x, P, v0[r]); v1[r] = f2fma(wv3.y, P, v1[r]);
                    }
                    #pragma unroll
                    for (int r = 0; r < 4; r++) {
                        ull t0 = f2mul(rh2, v0[r]);
                        m1a[nn][r] = f2add(m1a[nn][r], t0);
                        m2a[nn][r] = f2fma(t0, v0[r], m2a[nn][r]);
                        ull t1 = f2mul(rh2, v1[r]);
                        m1b[nn][r] = f2add(m1b[nn][r], t1);
                        m2b[nn][r] = f2fma(t1, v1[r], m2b[nn][r]);
                    }
                }
            }
        }
        __syncthreads();   // all ph reads done before red overwrites it

        // two-pass reduction (red region = 16*1056 floats, aliased on ph)
        #pragma unroll 1
        for (int nn = 0; nn < 2; nn++) {
            float* myred = red + (w * 32 + c) * 33;
            #pragma unroll
            for (int r = 0; r < 4; r++) {
                float lo, hi;
                f2unpack(lo, hi, m1a[nn][r]); myred[r]      = lo; myred[4 + r]  = hi;
                f2unpack(lo, hi, m1b[nn][r]); myred[8 + r]  = lo; myred[12 + r] = hi;
                f2unpack(lo, hi, m2a[nn][r]); myred[16 + r] = lo; myred[20 + r] = hi;
                f2unpack(lo, hi, m2b[nn][r]); myred[24 + r] = lo; myred[28 + r] = hi;
            }
            myred[32] = sumr[nn];
            __syncthreads();
            for (int s = tid; s < 1056; s += 512) {
                float acc = 0.0f;
                #pragma unroll
                for (int ww = 0; ww < 16; ww++) acc += red[ww * 1056 + s];
                mom[nn * 1056 + s] = acc;
            }
            __syncthreads();
        }

        // ================= stats (64 threads: c x nn) =================
        if (tid < 64) {
            int nn = tid >> 5, cc = tid & 31;
            const float* mm = mom + nn * 1056 + cc * 33;
            float R = mm[32];
            float invR = 1.0f / R;
            float cs = 0.0f;
            #pragma unroll
            for (int d = 0; d < 16; d++) {
                float m  = mm[d] * invR;
                float sg = fmaf(-m, m, mm[16 + d] * invR);
                mu_s[nn * 544 + cc * 17 + d] = m;
                cs += __logf(sg);
            }
            float cost = R * fmaf(16.0f, bv, cs);
            float act  = 1.0f / (1.0f + __expf(lam * (cost - ba)));
            if (it == 2) {
                float* on = out + (long)(2 * np + nn) * 19584 + xy;
                #pragma unroll
                for (int d = 0; d < 16; d++)
                    on[(cc * 16 + d) * 36] = mu_s[nn * 544 + cc * 17 + d];
                on[(512 + cc) * 36] = act;
            } else {
                sfac_s[nn * 32 + cc] = act * __expf(-0.5f * fmaf(16.0f, LOG2PI, cs));
            }
        }
        __syncthreads();
        if (it == 2) return;

        // ================= E phase =================
        {
            float sf0 = sfac_s[c], sf1 = sfac_s[32 + c];
            ull nmu0[2][4], nmu1[2][4];
            #pragma unroll
            for (int nn = 0; nn < 2; nn++)
                #pragma unroll
                for (int r = 0; r < 4; r++) {
                    const float* mc = mu_s + nn * 544 + c * 17;
                    nmu0[nn][r] = f2pack(-mc[r],     -mc[4 + r]);
                    nmu1[nn][r] = f2pack(-mc[8 + r], -mc[12 + r]);
                }
            #pragma unroll 1
            for (int oo = 0; oo < 2; oo++) {
                int o = w * 2 + oo;
                #pragma unroll 3
                for (int ij = 0; ij < 9; ij++) {
                    int oij = o * 9 + ij;
                    const ulonglong2* wp = (const ulonglong2*)g_Wt + (oij * 4) * 32 + c;
                    ulonglong2 wv0 = wp[0], wv1 = wp[32], wv2 = wp[64], wv3 = wp[96];
                    int i2 = ij / 3, j2 = ij - i2 * 3;
                    int pslot = (o * 9 + ((3 - i2) % 3) * 3 + ((3 - j2) % 3)) * 33 + c;
                    #pragma unroll
                    for (int nn = 0; nn < 2; nn++) {
                        const ull* pb = (const ull*)(pose2 + nn * 9216 + oij * 32);
                        ull v0[4], v1[4];
                        #pragma unroll
                        for (int r = 0; r < 4; r++) {
                            ull P = pb[r];
                            v0[r] = f2mul(wv0.x, P); v1[r] = f2mul(wv0.y, P);
                        }
                        #pragma unroll
                        for (int r = 0; r < 4; r++) {
                            ull P = pb[4 + r];
                            v0[r] = f2fma(wv1.x, P, v0[r]); v1[r] = f2fma(wv1.y, P, v1[r]);
                        }
                        #pragma unroll
                        for (int r = 0; r < 4; r++) {
                            ull P = pb[8 + r];
                            v0[r] = f2fma(wv2.x, P, v0[r]); v1[r] = f2fma(wv2.y, P, v1[r]);
                        }
                        #pragma unroll
                        for (int r = 0; r < 4; r++) {
                            ull P = pb[12 + r];
                            v0[r] = f2fma(wv3.x, P, v0[r]); v1[r] = f2fma(wv3.y, P, v1[r]);
                        }
                        ull ssd2;
                        {
                            ull dd = f2add(v0[0], nmu0[nn][0]);
                            ssd2 = f2mul(dd, dd);
                        }
                        #pragma unroll
                        for (int r = 1; r < 4; r++) {
                            ull dd = f2add(v0[r], nmu0[nn][r]);
                            ssd2 = f2fma(dd, dd, ssd2);
                        }
                        #pragma unroll
                        for (int r = 0; r < 4; r++) {
                            ull dd = f2add(v1[r], nmu1[nn][r]);
                            ssd2 = f2fma(dd, dd, ssd2);
                        }
                        float slo, shi; f2unpack(slo, shi, ssd2);
                        float ph = (nn ? sf1 : sf0) * __expf(-(slo + shi));
                        // kperm=[0,2,1] self-inverse: file p_hat at permuted slot
                        ph_s[nn * 9504 + pslot] = ph;
                    }
                }
            }
        }
        __syncthreads();

        // ---- D pass: 576 row sums -> global atomics ----
        float* Dg = (it == 0) ? g_D0 : g_D1;
        for (int row = tid; row < 576; row += 512) {
            int nn = (row >= 288) ? 1 : 0;
            int oij = row - nn * 288;
            const float* pr = ph_s + nn * 9504 + oij * 33;
            float s = 0.0f;
            #pragma unroll
            for (int k = 0; k < 32; k++) s += pr[k];
            int o = oij / 9, ij = oij - o * 9;
            atomicAdd(&Dg[((2 * np + nn) * 32 + o) * 169 + (2 * X + ij / 3) * 13 + (2 * Y + ij % 3)], s);
        }

        // ---- grid barrier (144 blocks, all provably co-resident) ----
        __syncthreads();
        if (tid == 0) {
            __threadfence();
            atomicAdd(&g_bar[it], 1u);
            while (*((volatile unsigned*)&g_bar[it]) < 144u) { __nanosleep(32); }
        }
        __syncthreads();

        // ---- aD pass: a / D ----
        for (int e = tid; e < 576; e += 512) {
            int nn = (e >= 288) ? 1 : 0;
            int oij = e - nn * 288;
            int o = oij / 9, ij = oij - o * 9;
            float Dv = __ldcg(&Dg[((2 * np + nn) * 32 + o) * 169 + (2 * X + ij / 3) * 13 + (2 * Y + ij % 3)]);
            aD_s[e] = __fdividef(a_s[e], Dv);
        }
        __syncthreads();
    }
}

extern "C" void kernel_launch(void* const* d_in, const int* in_sizes, int n_in,
                              void* d_out, int out_size) {
    const float* x   = (const float*)d_in[0];
    const float* W   = (const float*)d_in[1];
    const float* bv  = (const float*)d_in[2];
    const float* ba  = (const float*)d_in[3];
    const float* lam = (const float*)d_in[4];
    float* out = (float*)d_out;

    const int smem = SMEM_FLOATS * 4;   // 167424 B
    cudaFuncSetAttribute(fused_kernel, cudaFuncAttributeMaxDynamicSharedMemorySize, smem);

    prep_kernel<<<576, 256>>>(W);
    fused_kernel<<<dim3(36, 4), 512, smem>>>(x, bv, ba, lam, out);
}

// round 6
// speedup vs baseline: 1.1815x; 1.1815x over previous
#include <cuda_runtime.h>
#include <math.h>

// ConvCaps EM routing (b=8, B=C=32, K=3, s=2, Win=13, Wout=6, 3 EM iters).
// Fused persistent kernel (R4 structure: block=(n,xy), 256 thr, 2 blocks/SM).
// This round: pose smem reads vectorized to LDS.128 (halves pose LSU cycles).
// p_hat block-local in smem; grid barrier only for the D normalizer.
// Vote math in packed fma.rn.f32x2 (d-pairs over p; pose duplicated in smem).

#define RP0 (1.0f / 1152.0f)
#define LOG2PI 1.8378770664093453f
typedef unsigned long long ull;

__device__ float g_Wt[147456];   // [o][ij][q][c][p]  (ulonglong2 per (q,c))
__device__ float g_D0[43264];    // [n][o][13][13]
__device__ float g_D1[43264];
__device__ unsigned g_bar[2];

// -------- prep: W relayout, zero D + barrier counters --------
__global__ void prep_kernel(const float* __restrict__ W) {
    int idx = blockIdx.x * 256 + threadIdx.x;
    if (idx < 147456) {
        int p = idx & 3, c = (idx >> 2) & 31, q = (idx >> 7) & 3;
        int oij = idx >> 9;
        int o = oij / 9, ij = oij - o * 9;
        // src: W[i,j,o,c,p,q]
        g_Wt[idx] = W[(((ij * 32 + o) * 32 + c) * 4 + p) * 4 + q];
    }
    if (idx < 43264) { g_D0[idx] = 0.0f; g_D1[idx] = 0.0f; }
    if (idx < 2) g_bar[idx] = 0u;
}

// -------- packed f32x2 helpers --------
__device__ __forceinline__ ull f2fma(ull a, ull b, ull c) {
    ull d; asm("fma.rn.f32x2 %0, %1, %2, %3;" : "=l"(d) : "l"(a), "l"(b), "l"(c)); return d;
}
__device__ __forceinline__ ull f2mul(ull a, ull b) {
    ull d; asm("mul.rn.f32x2 %0, %1, %2;" : "=l"(d) : "l"(a), "l"(b)); return d;
}
__device__ __forceinline__ ull f2add(ull a, ull b) {
    ull d; asm("add.rn.f32x2 %0, %1, %2;" : "=l"(d) : "l"(a), "l"(b)); return d;
}
__device__ __forceinline__ ull f2pack(float lo, float hi) {
    ull d; asm("mov.b64 %0, {%1, %2};" : "=l"(d) : "f"(lo), "f"(hi)); return d;
}
__device__ __forceinline__ void f2unpack(float& lo, float& hi, ull v) {
    asm("mov.b64 {%0, %1}, %2;" : "=f"(lo), "=f"(hi) : "l"(v));
}

// smem float offsets
#define SM_POSE2 0        // [oij][qr][2] duplicated pose: 9216
#define SM_A     9216     // 288
#define SM_AD    9504     // 288
#define SM_PH    9792     // [oij][33] p_hat (red 8*1056=8448 aliased): 9504
#define SM_MOM   19296    // [c][33]: 1056
#define SM_MU    20352    // [c][17]: 544
#define SM_SFAC  20896    // 32
#define SMEM_FLOATS 20928

__global__ void __launch_bounds__(256, 2) fused_kernel(
    const float* __restrict__ x,
    const float* __restrict__ bv_p,
    const float* __restrict__ ba_p,
    const float* __restrict__ lam_p,
    float* __restrict__ out)
{
    extern __shared__ float sm[];
    float* pose2  = sm + SM_POSE2;
    float* a_s    = sm + SM_A;
    float* aD_s   = sm + SM_AD;
    float* ph_s   = sm + SM_PH;
    float* red    = ph_s;          // aliased: red live only between M and stats
    float* mom    = sm + SM_MOM;
    float* mu_s   = sm + SM_MU;
    float* sfac_s = sm + SM_SFAC;

    const int xy = blockIdx.x;     // 0..35
    const int n  = blockIdx.y;     // 0..7
    const int X = xy / 6, Y = xy % 6;
    const int tid = threadIdx.x;
    const int w = tid >> 5;
    const int c = tid & 31;

    const float* xn = x + n * (544 * 169);
    const int base = (2 * X) * 13 + 2 * Y;

    // ---- load patch: duplicated pose (qr-inner), act ----
    for (int e = tid; e < 512; e += 256) {
        int qr = e & 15, o = e >> 4;
        const float* src = xn + (qr * 32 + o) * 169 + base;
        #pragma unroll
        for (int i = 0; i < 3; i++)
            #pragma unroll
            for (int j = 0; j < 3; j++) {
                float v = src[i * 13 + j];
                int off = (o * 9 + i * 3 + j) * 32 + qr * 2;
                pose2[off] = v; pose2[off + 1] = v;
            }
    }
    for (int e = tid; e < 288; e += 256) {
        int o = e / 9, ij = e - o * 9;
        float av = xn[(512 + o) * 169 + base + (ij / 3) * 13 + (ij % 3)];
        a_s[e] = av;
        aD_s[e] = av * RP0;        // iter0: rh = ph(=1) * aD
    }
    for (int e = tid; e < 9504; e += 256) ph_s[e] = 1.0f;
    __syncthreads();

    const float bv = bv_p[0], ba = ba_p[0], lam = lam_p[0];

    for (int it = 0; it < 3; it++) {
        // ================= M phase =================
        ull m1a[4], m1b[4], m2a[4], m2b[4];
        #pragma unroll
        for (int r = 0; r < 4; r++) { m1a[r]=0ull; m1b[r]=0ull; m2a[r]=0ull; m2b[r]=0ull; }
        float sumr = 0.0f;

        #pragma unroll 1
        for (int oo = 0; oo < 4; oo++) {
            int o = w * 4 + oo;
            #pragma unroll 3
            for (int ij = 0; ij < 9; ij++) {
                int oij = o * 9 + ij;
                float rh = ph_s[oij * 33 + c] * aD_s[oij];
                sumr += rh;
                ull rh2 = f2pack(rh, rh);
                const ulonglong2* pb2 = (const ulonglong2*)(pose2 + oij * 32);
                const ulonglong2* wp = (const ulonglong2*)g_Wt + (oij * 4) * 32 + c;
                ull v0[4], v1[4];
                {
                    ulonglong2 wv = wp[0];
                    ulonglong2 pA = pb2[0], pB = pb2[1];      // q=0: dup P r0..r3
                    v0[0] = f2mul(wv.x, pA.x); v1[0] = f2mul(wv.y, pA.x);
                    v0[1] = f2mul(wv.x, pA.y); v1[1] = f2mul(wv.y, pA.y);
                    v0[2] = f2mul(wv.x, pB.x); v1[2] = f2mul(wv.y, pB.x);
                    v0[3] = f2mul(wv.x, pB.y); v1[3] = f2mul(wv.y, pB.y);
                }
                #pragma unroll
                for (int q = 1; q < 4; q++) {
                    ulonglong2 wv = wp[q * 32];
                    ulonglong2 pA = pb2[q * 2], pB = pb2[q * 2 + 1];
                    v0[0] = f2fma(wv.x, pA.x, v0[0]); v1[0] = f2fma(wv.y, pA.x, v1[0]);
                    v0[1] = f2fma(wv.x, pA.y, v0[1]); v1[1] = f2fma(wv.y, pA.y, v1[1]);
                    v0[2] = f2fma(wv.x, pB.x, v0[2]); v1[2] = f2fma(wv.y, pB.x, v1[2]);
                    v0[3] = f2fma(wv.x, pB.y, v0[3]); v1[3] = f2fma(wv.y, pB.y, v1[3]);
                }
                #pragma unroll
                for (int r = 0; r < 4; r++) {
                    ull t0 = f2mul(rh2, v0[r]);
                    m1a[r] = f2add(m1a[r], t0);
                    m2a[r] = f2fma(t0, v0[r], m2a[r]);
                    ull t1 = f2mul(rh2, v1[r]);
                    m1b[r] = f2add(m1b[r], t1);
                    m2b[r] = f2fma(t1, v1[r], m2b[r]);
                }
            }
        }
        __syncthreads();   // all ph reads done before red overwrites it

        // pair layout: v0[r] = (d=r, d=4+r), v1[r] = (d=8+r, d=12+r)
        {
            float* myred = red + (w * 32 + c) * 33;
            #pragma unroll
            for (int r = 0; r < 4; r++) {
                float lo, hi;
                f2unpack(lo, hi, m1a[r]); myred[r]      = lo; myred[4 + r]  = hi;
                f2unpack(lo, hi, m1b[r]); myred[8 + r]  = lo; myred[12 + r] = hi;
                f2unpack(lo, hi, m2a[r]); myred[16 + r] = lo; myred[20 + r] = hi;
                f2unpack(lo, hi, m2b[r]); myred[24 + r] = lo; myred[28 + r] = hi;
            }
            myred[32] = sumr;
        }
        __syncthreads();
        for (int s = tid; s < 1056; s += 256) {
            float acc = 0.0f;
            #pragma unroll
            for (int ww = 0; ww < 8; ww++) acc += red[ww * 1056 + s];
            mom[s] = acc;
        }
        __syncthreads();

        // ================= stats =================
        if (tid < 32) {
            const float* mm = mom + tid * 33;
            float R = mm[32];
            float invR = 1.0f / R;
            float cs = 0.0f;
            #pragma unroll
            for (int d = 0; d < 16; d++) {
                float m  = mm[d] * invR;
                float sg = fmaf(-m, m, mm[16 + d] * invR);
                mu_s[tid * 17 + d] = m;
                cs += __logf(sg);
            }
            float cost = R * fmaf(16.0f, bv, cs);
            float act  = 1.0f / (1.0f + __expf(lam * (cost - ba)));
            if (it == 2) {
                float* on = out + (long)n * 19584 + xy;
                #pragma unroll
                for (int d = 0; d < 16; d++)
                    on[(tid * 16 + d) * 36] = mu_s[tid * 17 + d];
                on[(512 + tid) * 36] = act;
            } else {
                sfac_s[tid] = act * __expf(-0.5f * fmaf(16.0f, LOG2PI, cs));
            }
        }
        __syncthreads();
        if (it == 2) return;

        // ================= E phase =================
        {
            float sf = sfac_s[c];
            ull nmu0[4], nmu1[4];
            #pragma unroll
            for (int r = 0; r < 4; r++) {
                nmu0[r] = f2pack(-mu_s[c * 17 + r],     -mu_s[c * 17 + 4 + r]);
                nmu1[r] = f2pack(-mu_s[c * 17 + 8 + r], -mu_s[c * 17 + 12 + r]);
            }
            #pragma unroll 1
            for (int oo = 0; oo < 4; oo++) {
                int o = w * 4 + oo;
                #pragma unroll 3
                for (int ij = 0; ij < 9; ij++) {
                    int oij = o * 9 + ij;
                    const ulonglong2* pb2 = (const ulonglong2*)(pose2 + oij * 32);
                    const ulonglong2* wp = (const ulonglong2*)g_Wt + (oij * 4) * 32 + c;
                    ull v0[4], v1[4];
                    {
                        ulonglong2 wv = wp[0];
                        ulonglong2 pA = pb2[0], pB = pb2[1];
                        v0[0] = f2mul(wv.x, pA.x); v1[0] = f2mul(wv.y, pA.x);
                        v0[1] = f2mul(wv.x, pA.y); v1[1] = f2mul(wv.y, pA.y);
                        v0[2] = f2mul(wv.x, pB.x); v1[2] = f2mul(wv.y, pB.x);
                        v0[3] = f2mul(wv.x, pB.y); v1[3] = f2mul(wv.y, pB.y);
                    }
                    #pragma unroll
                    for (int q = 1; q < 4; q++) {
                        ulonglong2 wv = wp[q * 32];
                        ulonglong2 pA = pb2[q * 2], pB = pb2[q * 2 + 1];
                        v0[0] = f2fma(wv.x, pA.x, v0[0]); v1[0] = f2fma(wv.y, pA.x, v1[0]);
                        v0[1] = f2fma(wv.x, pA.y, v0[1]); v1[1] = f2fma(wv.y, pA.y, v1[1]);
                        v0[2] = f2fma(wv.x, pB.x, v0[2]); v1[2] = f2fma(wv.y, pB.x, v1[2]);
                        v0[3] = f2fma(wv.x, pB.y, v0[3]); v1[3] = f2fma(wv.y, pB.y, v1[3]);
                    }
                    ull ssd2;
                    {
                        ull dd = f2add(v0[0], nmu0[0]);
                        ssd2 = f2mul(dd, dd);
                    }
                    #pragma unroll
                    for (int r = 1; r < 4; r++) {
                        ull dd = f2add(v0[r], nmu0[r]);
                        ssd2 = f2fma(dd, dd, ssd2);
                    }
                    #pragma unroll
                    for (int r = 0; r < 4; r++) {
                        ull dd = f2add(v1[r], nmu1[r]);
                        ssd2 = f2fma(dd, dd, ssd2);
                    }
                    float slo, shi; f2unpack(slo, shi, ssd2);
                    float ph = sf * __expf(-(slo + shi));
                    // kperm=[0,2,1] self-inverse: file p_hat at permuted slot
                    int i2 = ij / 3, j2 = ij - i2 * 3;
                    ph_s[(o * 9 + ((3 - i2) % 3) * 3 + ((3 - j2) % 3)) * 33 + c] = ph;
                }
            }
        }
        __syncthreads();

        // ---- D pass: row sums -> global atomics ----
        float* Dg = (it == 0) ? g_D0 : g_D1;
        for (int row = tid; row < 288; row += 256) {
            const float* pr = ph_s + row * 33;
            float s = 0.0f;
            #pragma unroll
            for (int k = 0; k < 32; k++) s += pr[k];
            int o = row / 9, ij = row - o * 9;
            atomicAdd(&Dg[(n * 32 + o) * 169 + (2 * X + ij / 3) * 13 + (2 * Y + ij % 3)], s);
        }

        // ---- grid barrier (288 blocks, 2/SM provably co-resident) ----
        __syncthreads();
        if (tid == 0) {
            __threadfence();
            atomicAdd(&g_bar[it], 1u);
            while (*((volatile unsigned*)&g_bar[it]) < 288u) { __nanosleep(32); }
        }
        __syncthreads();

        // ---- aD pass: a / D ----
        for (int e = tid; e < 288; e += 256) {
            int o = e / 9, ij = e - o * 9;
            float Dv = __ldcg(&Dg[(n * 32 + o) * 169 + (2 * X + ij / 3) * 13 + (2 * Y + ij % 3)]);
            aD_s[e] = __fdividef(a_s[e], Dv);
        }
        __syncthreads();
    }
}

extern "C" void kernel_launch(void* const* d_in, const int* in_sizes, int n_in,
                              void* d_out, int out_size) {
    const float* x   = (const float*)d_in[0];
    const float* W   = (const float*)d_in[1];
    const float* bv  = (const float*)d_in[2];
    const float* ba  = (const float*)d_in[3];
    const float* lam = (const float*)d_in[4];
    float* out = (float*)d_out;

    const int smem = SMEM_FLOATS * 4;   // 83712 B
    cudaFuncSetAttribute(fused_kernel, cudaFuncAttributeMaxDynamicSharedMemorySize, smem);

    prep_kernel<<<576, 256>>>(W);
    fused_kernel<<<dim3(36, 8), 256, smem>>>(x, bv, ba, lam, out);
}